// round 7
// baseline (speedup 1.0000x reference)
#include <cuda_runtime.h>
#include <cuda_bf16.h>
#include <math.h>
#include <stdint.h>

#define NN 50000
#define EE 800000

// ---------------- scratch (no cudaMalloc allowed) ----------------
__device__ __align__(16) float g_v[NN * 64];
__device__ __align__(16) float g_agg[NN * 64];
__device__ __align__(16) float g_rbf[EE * 12];
// bf16 hi/lo activations
__device__ __align__(16) __nv_bfloat16 g_xh[NN * 256];
__device__ __align__(16) __nv_bfloat16 g_xl[NN * 256];
__device__ __align__(16) __nv_bfloat16 g_th[NN * 256];
__device__ __align__(16) __nv_bfloat16 g_tl[NN * 256];
__device__ __align__(16) __nv_bfloat16 g_aggh[NN * 64];
__device__ __align__(16) __nv_bfloat16 g_aggl[NN * 64];
// bf16 hi/lo transposed weights: 10x[256x256] + 8x[64x256 / 256x64]
__device__ __align__(16) __nv_bfloat16 g_wh[10 * 65536 + 8 * 16384];
__device__ __align__(16) __nv_bfloat16 g_wl[10 * 65536 + 8 * 16384];

__device__ __forceinline__ uint32_t smem_u32(const void* p) {
    uint32_t a;
    asm("{ .reg .u64 t; cvta.to.shared.u64 t, %1; cvt.u32.u64 %0, t; }" : "=r"(a) : "l"(p));
    return a;
}

__device__ __forceinline__ void ldsm4(uint32_t& r0, uint32_t& r1, uint32_t& r2,
                                      uint32_t& r3, uint32_t addr) {
    asm volatile("ldmatrix.sync.aligned.m8n8.x4.shared.b16 {%0,%1,%2,%3}, [%4];"
                 : "=r"(r0), "=r"(r1), "=r"(r2), "=r"(r3) : "r"(addr));
}

__device__ __forceinline__ void mma_bf16(float* c, const uint32_t* a, const uint32_t* b) {
    asm volatile(
        "mma.sync.aligned.m16n8k16.row.col.f32.bf16.bf16.f32 "
        "{%0,%1,%2,%3}, {%4,%5,%6,%7}, {%8,%9}, {%0,%1,%2,%3};"
        : "+f"(c[0]), "+f"(c[1]), "+f"(c[2]), "+f"(c[3])
        : "r"(a[0]), "r"(a[1]), "r"(a[2]), "r"(a[3]), "r"(b[0]), "r"(b[1]));
}

__device__ __forceinline__ float gelu_f(float x) {
    float x3 = x * x * x;
    float t = tanhf(0.7978845608028654f * (x + 0.044715f * x3));
    return 0.5f * x * (1.0f + t);
}

__device__ __forceinline__ void split_bf16(float v, __nv_bfloat16& h, __nv_bfloat16& l) {
    h = __float2bfloat16(v);
    l = __float2bfloat16(v - __bfloat162float(h));
}

// ---------------------------------------------------------------------------
// Weight convert: W [nm][K x N] fp32 -> out [nm][N x K] bf16 hi/lo (transposed)
// ---------------------------------------------------------------------------
__global__ void conv_w_kernel(const float* __restrict__ W,
                              __nv_bfloat16* __restrict__ oh,
                              __nv_bfloat16* __restrict__ ol,
                              int K, int Ncols, int total) {
    int idx = blockIdx.x * blockDim.x + threadIdx.x;
    if (idx >= total) return;
    int kn = K * Ncols;
    int m = idx / kn;
    int r = idx - m * kn;
    int n = r / K;
    int k = r - n * K;
    float w = W[(size_t)m * kn + (size_t)k * Ncols + n];
    split_bf16(w, oh[idx], ol[idx]);
}

// ---------------------------------------------------------------------------
// HMMA GEMM: pre-split bf16 A/B, register-prefetch + double-buffered smem,
// one __syncthreads per k-chunk. BM=128, BN=64, BK=32, 256 thr, 8 warps.
// 3-product split: Ah*Bh + Ah*Bl + Al*Bh, fp32 accumulate.
// ---------------------------------------------------------------------------
template <bool BIAS, bool GELU, bool RESID, bool OUTF32, bool OUTSPLIT>
__global__ void __launch_bounds__(256, 2) mma_gemm(
    const __nv_bfloat16* __restrict__ Ah_g,
    const __nv_bfloat16* __restrict__ Al_g,
    const __nv_bfloat16* __restrict__ Bh_g,
    const __nv_bfloat16* __restrict__ Bl_g,
    const float* __restrict__ bias,
    float* __restrict__ C,
    __nv_bfloat16* __restrict__ Oh,
    __nv_bfloat16* __restrict__ Ol,
    int rows, int K, int ncols)
{
    constexpr int BM = 128, BN = 64, BK = 32, LD = 40;
    // per-stage byte layout: AH[10240] AL[10240] BH[5120] BL[5120] = 30720
    constexpr int STG = 30720;
    constexpr int OAL = 10240, OBH = 20480, OBL = 25600;
    extern __shared__ char smem[];

    int tid = threadIdx.x;
    int lane = tid & 31;
    int wid = tid >> 5;
    int wm = wid & 3;
    int wn = wid >> 2;
    int r0 = blockIdx.y * BM;
    int c0 = blockIdx.x * BN;

    uint32_t sb = smem_u32(smem);

    float acc[2][4][4];
#pragma unroll
    for (int i = 0; i < 2; i++)
#pragma unroll
        for (int j = 0; j < 4; j++)
#pragma unroll
            for (int k = 0; k < 4; k++) acc[i][j][k] = 0.f;

    int a_r = lane & 15;
    int a_c = (lane >> 4) * 8;
    int b_n = ((lane >> 4) * 8) + (lane & 7);
    int b_k = ((lane >> 3) & 1) * 8;

    // per-thread load mapping
    int ar0 = tid >> 2;            // A chunk 0 row (0..63)
    int ar1 = ar0 + 64;            // A chunk 1 row (64..127)
    int ac16 = tid & 3;            // 16B chunk in row
    int brow = tid >> 2;           // B row (0..63)
    int bc16 = tid & 3;

    uint4 pa_h[2], pa_l[2], pb_h, pb_l;
    const uint4 Z = make_uint4(0, 0, 0, 0);

    auto ldg_chunk = [&](int kc) {
        int k0 = kc * BK;
        int g0 = r0 + ar0, g1 = r0 + ar1;
        size_t i0 = (size_t)g0 * K + k0 + ac16 * 8;
        size_t i1 = (size_t)g1 * K + k0 + ac16 * 8;
        pa_h[0] = (g0 < rows) ? *reinterpret_cast<const uint4*>(Ah_g + i0) : Z;
        pa_l[0] = (g0 < rows) ? *reinterpret_cast<const uint4*>(Al_g + i0) : Z;
        pa_h[1] = (g1 < rows) ? *reinterpret_cast<const uint4*>(Ah_g + i1) : Z;
        pa_l[1] = (g1 < rows) ? *reinterpret_cast<const uint4*>(Al_g + i1) : Z;
        size_t ib = (size_t)(c0 + brow) * K + k0 + bc16 * 8;
        pb_h = *reinterpret_cast<const uint4*>(Bh_g + ib);
        pb_l = *reinterpret_cast<const uint4*>(Bl_g + ib);
    };

    auto sts_chunk = [&](int s) {
        uint32_t base = (uint32_t)s * STG;
        uint32_t da0 = base + (uint32_t)((ar0 * LD + ac16 * 8) * 2);
        uint32_t da1 = base + (uint32_t)((ar1 * LD + ac16 * 8) * 2);
        *reinterpret_cast<uint4*>(smem + da0) = pa_h[0];
        *reinterpret_cast<uint4*>(smem + da1) = pa_h[1];
        *reinterpret_cast<uint4*>(smem + OAL + da0) = pa_l[0];
        *reinterpret_cast<uint4*>(smem + OAL + da1) = pa_l[1];
        uint32_t db = base + (uint32_t)((brow * LD + bc16 * 8) * 2);
        *reinterpret_cast<uint4*>(smem + OBH + db) = pb_h;
        *reinterpret_cast<uint4*>(smem + OBL + db) = pb_l;
    };

    int nkc = K / BK;
    ldg_chunk(0);
    sts_chunk(0);
    __syncthreads();

    for (int kc = 0; kc < nkc; kc++) {
        int s = kc & 1;
        if (kc + 1 < nkc) ldg_chunk(kc + 1);   // LDG overlaps compute below

        uint32_t aHb = sb + (uint32_t)s * STG;
        uint32_t aLb = aHb + OAL;
        uint32_t bHb = sb + (uint32_t)s * STG + OBH;
        uint32_t bLb = sb + (uint32_t)s * STG + OBL;
#pragma unroll
        for (int kk = 0; kk < 2; kk++) {
            uint32_t ah[2][4], al[2][4], bh[2][4], bl[2][4];
#pragma unroll
            for (int im = 0; im < 2; im++) {
                uint32_t off = (uint32_t)(((wm * 32 + im * 16 + a_r) * LD + kk * 16 + a_c) * 2);
                ldsm4(ah[im][0], ah[im][1], ah[im][2], ah[im][3], aHb + off);
                ldsm4(al[im][0], al[im][1], al[im][2], al[im][3], aLb + off);
            }
#pragma unroll
            for (int jp = 0; jp < 2; jp++) {
                uint32_t off = (uint32_t)(((wn * 32 + jp * 16 + b_n) * LD + kk * 16 + b_k) * 2);
                ldsm4(bh[jp][0], bh[jp][1], bh[jp][2], bh[jp][3], bHb + off);
                ldsm4(bl[jp][0], bl[jp][1], bl[jp][2], bl[jp][3], bLb + off);
            }
#pragma unroll
            for (int im = 0; im < 2; im++)
#pragma unroll
                for (int jn = 0; jn < 4; jn++) {
                    const uint32_t* pbh = &bh[jn >> 1][(jn & 1) * 2];
                    const uint32_t* pbl = &bl[jn >> 1][(jn & 1) * 2];
                    mma_bf16(acc[im][jn], ah[im], pbh);
                    mma_bf16(acc[im][jn], ah[im], pbl);
                    mma_bf16(acc[im][jn], al[im], pbh);
                }
        }
        if (kc + 1 < nkc) sts_chunk(s ^ 1);
        __syncthreads();
    }

    // --- epilogue ---
#pragma unroll
    for (int im = 0; im < 2; im++) {
        int rowa = r0 + wm * 32 + im * 16 + (lane >> 2);
#pragma unroll
        for (int jn = 0; jn < 4; jn++) {
            int col = c0 + wn * 32 + jn * 8 + (lane & 3) * 2;
            float2 bv = make_float2(0.f, 0.f);
            if (BIAS) bv = *reinterpret_cast<const float2*>(bias + col);
#pragma unroll
            for (int h = 0; h < 2; h++) {
                int row = rowa + h * 8;
                if (row >= rows) continue;
                float vx = acc[im][jn][h * 2 + 0];
                float vy = acc[im][jn][h * 2 + 1];
                if (BIAS) { vx += bv.x; vy += bv.y; }
                if (GELU) { vx = gelu_f(vx); vy = gelu_f(vy); }
                size_t idx = (size_t)row * ncols + col;
                if (RESID) {
                    float2 old = *reinterpret_cast<const float2*>(C + idx);
                    vx += old.x; vy += old.y;
                }
                if (OUTF32)
                    *reinterpret_cast<float2*>(C + idx) = make_float2(vx, vy);
                if (OUTSPLIT) {
                    __nv_bfloat16 hx, lx, hy, ly;
                    split_bf16(vx, hx, lx);
                    split_bf16(vy, hy, ly);
                    *reinterpret_cast<__nv_bfloat162*>(Oh + idx) = __nv_bfloat162(hx, hy);
                    *reinterpret_cast<__nv_bfloat162*>(Ol + idx) = __nv_bfloat162(lx, ly);
                }
            }
        }
    }
}

// ---------------------------------------------------------------------------
// Embedding init -> bf16 hi/lo
// ---------------------------------------------------------------------------
__global__ void embed_kernel(const int* __restrict__ z,
                             const float* __restrict__ table,
                             const float* __restrict__ W,
                             const float* __restrict__ b, int N) {
    int n = blockIdx.x;
    if (n >= N) return;
    int d = threadIdx.x;
    int t = z[n];
    float acc = b[d];
#pragma unroll
    for (int h = 0; h < 5; h++) acc += table[t * 5 + h] * W[h * 256 + d];
    __nv_bfloat16 hh, ll;
    split_bf16(acc, hh, ll);
    g_xh[(size_t)n * 256 + d] = hh;
    g_xl[(size_t)n * 256 + d] = ll;
}

// ---------------------------------------------------------------------------
// agg fp32 -> bf16 hi/lo
// ---------------------------------------------------------------------------
__global__ void split_agg_kernel(int total) {
    int idx = blockIdx.x * blockDim.x + threadIdx.x;
    if (idx >= total) return;
    split_bf16(g_agg[idx], g_aggh[idx], g_aggl[idx]);
}

// ---------------------------------------------------------------------------
// Bessel RBF with polynomial envelope (p=5)
// ---------------------------------------------------------------------------
__global__ void rbf_kernel(const int* __restrict__ ei,
                           const float* __restrict__ pos,
                           const float* __restrict__ freqs,
                           int E) {
    int e = blockIdx.x * blockDim.x + threadIdx.x;
    if (e >= E) return;
    int i = ei[e];
    int j = ei[E + e];
    float dx = pos[i * 3 + 0] - pos[j * 3 + 0];
    float dy = pos[i * 3 + 1] - pos[j * 3 + 1];
    float dz = pos[i * 3 + 2] - pos[j * 3 + 2];
    float dist = sqrtf(dx * dx + dy * dy + dz * dz + 1e-12f);
    float x = dist * 0.2f;
    float x2 = x * x;
    float x4 = x2 * x2;
    float env = 1.0f / x + (-21.0f) * x4 + 35.0f * x4 * x + (-15.0f) * x4 * x2;
#pragma unroll
    for (int r = 0; r < 12; r++)
        g_rbf[(size_t)e * 12 + r] = env * sinf(freqs[r] * x);
}

// ---------------------------------------------------------------------------
// Edge messages + scatter: 16 threads/edge, vector red.global.add.v4.f32
// ---------------------------------------------------------------------------
__global__ void edge_msg_kernel(const int* __restrict__ ei,
                                const float* __restrict__ Wrbf,  // [12,64]
                                int E) {
    __shared__ float sW[12 * 64];
    for (int t = threadIdx.x; t < 12 * 64; t += blockDim.x) sW[t] = Wrbf[t];
    __syncthreads();

    int gt = blockIdx.x * blockDim.x + threadIdx.x;
    int e = gt >> 4;
    if (e >= E) return;
    int sub = gt & 15;
    int m0 = sub * 4;

    int i = ei[e];
    int j = ei[E + e];

    float gx = 0.f, gy = 0.f, gz = 0.f, gw = 0.f;
#pragma unroll
    for (int r = 0; r < 12; r++) {
        float rv = __ldg(&g_rbf[(size_t)e * 12 + r]);
        const float* w = &sW[r * 64 + m0];
        gx = fmaf(rv, w[0], gx);
        gy = fmaf(rv, w[1], gy);
        gz = fmaf(rv, w[2], gz);
        gw = fmaf(rv, w[3], gw);
    }
    const float4 vj = *reinterpret_cast<const float4*>(g_v + (size_t)j * 64 + m0);
    float vx = vj.x * gx, vy = vj.y * gy, vz = vj.z * gz, vw = vj.w * gw;
    float* dst = g_agg + (size_t)i * 64 + m0;
    asm volatile("red.global.add.v4.f32 [%0], {%1, %2, %3, %4};"
                 :: "l"(dst), "f"(vx), "f"(vy), "f"(vz), "f"(vw) : "memory");
}

// ---------------------------------------------------------------------------
// Launcher
// ---------------------------------------------------------------------------
extern "C" void kernel_launch(void* const* d_in, const int* in_sizes, int n_in,
                              void* d_out, int out_size) {
    const int* z = (const int*)d_in[0];
    const float* pos = (const float*)d_in[1];
    const int* ei = (const int*)d_in[4];
    const float* emb_table = (const float*)d_in[5];
    const float* emb_W = (const float*)d_in[6];
    const float* emb_b = (const float*)d_in[7];
    const float* freqs = (const float*)d_in[8];
    const float* fc0_W = (const float*)d_in[9];
    const float* fc0_b = (const float*)d_in[10];
    const float* conv_Wv = (const float*)d_in[11];
    const float* conv_Wrbf = (const float*)d_in[12];
    const float* conv_Wout = (const float*)d_in[13];
    const float* fc_W = (const float*)d_in[14];
    const float* fc_b = (const float*)d_in[15];

    int N = in_sizes[1] / 3;   // 50000
    int E = in_sizes[4] / 2;   // 800000

    float* x = (float*)d_out;

    float *vbuf, *agg;
    __nv_bfloat16 *wh, *wl, *xh, *xl, *th, *tl, *aggh, *aggl;
    cudaGetSymbolAddress((void**)&vbuf, g_v);
    cudaGetSymbolAddress((void**)&agg, g_agg);
    cudaGetSymbolAddress((void**)&wh, g_wh);
    cudaGetSymbolAddress((void**)&wl, g_wl);
    cudaGetSymbolAddress((void**)&xh, g_xh);
    cudaGetSymbolAddress((void**)&xl, g_xl);
    cudaGetSymbolAddress((void**)&th, g_th);
    cudaGetSymbolAddress((void**)&tl, g_tl);
    cudaGetSymbolAddress((void**)&aggh, g_aggh);
    cudaGetSymbolAddress((void**)&aggl, g_aggl);

    const int SMEM = 2 * 30720;  // 61440
    cudaFuncSetAttribute((const void*)mma_gemm<true, true, false, false, true>,
                         cudaFuncAttributeMaxDynamicSharedMemorySize, SMEM);
    cudaFuncSetAttribute((const void*)mma_gemm<true, true, false, true, true>,
                         cudaFuncAttributeMaxDynamicSharedMemorySize, SMEM);
    cudaFuncSetAttribute((const void*)mma_gemm<true, true, true, true, true>,
                         cudaFuncAttributeMaxDynamicSharedMemorySize, SMEM);
    cudaFuncSetAttribute((const void*)mma_gemm<false, false, false, true, false>,
                         cudaFuncAttributeMaxDynamicSharedMemorySize, SMEM);
    cudaFuncSetAttribute((const void*)mma_gemm<false, false, true, true, true>,
                         cudaFuncAttributeMaxDynamicSharedMemorySize, SMEM);

    // ---- weight conversion (hi/lo bf16, transposed) ----
    {
        int T = 2 * 65536;
        conv_w_kernel<<<(T + 255) / 256, 256>>>(fc0_W, wh, wl, 256, 256, T);
        T = 8 * 65536;
        conv_w_kernel<<<(T + 255) / 256, 256>>>(fc_W, wh + 2 * 65536, wl + 2 * 65536, 256, 256, T);
        T = 4 * 16384;
        conv_w_kernel<<<(T + 255) / 256, 256>>>(conv_Wv, wh + 655360, wl + 655360, 256, 64, T);
        conv_w_kernel<<<(T + 255) / 256, 256>>>(conv_Wout, wh + 655360 + 65536,
                                                wl + 655360 + 65536, 64, 256, T);
    }

    dim3 gridD(4, (N + 127) / 128);   // ncols=256
    dim3 gridM(1, (N + 127) / 128);   // ncols=64

    // 1. init embedding (split only)
    embed_kernel<<<N, 256>>>(z, emb_table, emb_W, emb_b, N);

    // 2. init FC block
    mma_gemm<true, true, false, false, true><<<gridD, 256, SMEM>>>(
        xh, xl, wh, wl, fc0_b, nullptr, th, tl, N, 256, 256);
    mma_gemm<true, true, false, true, true><<<gridD, 256, SMEM>>>(
        th, tl, wh + 65536, wl + 65536, fc0_b + 256, x, xh, xl, N, 256, 256);

    // 3. radial basis
    rbf_kernel<<<(E + 255) / 256, 256>>>(ei, pos, freqs, E);

    // 4. interaction blocks
    for (int n = 0; n < 4; n++) {
        cudaMemsetAsync(agg, 0, (size_t)N * 64 * sizeof(float));

        // v = x @ Wv[n]  (fp32 only)
        mma_gemm<false, false, false, true, false><<<gridM, 256, SMEM>>>(
            xh, xl, wh + 655360 + n * 16384, wl + 655360 + n * 16384, nullptr,
            vbuf, nullptr, nullptr, N, 256, 64);

        // gated messages + vector-red scatter
        edge_msg_kernel<<<(E * 16 + 255) / 256, 256>>>(
            ei, conv_Wrbf + (size_t)n * 12 * 64, E);

        // agg -> hi/lo
        split_agg_kernel<<<(N * 64 + 255) / 256, 256>>>(N * 64);

        // x = x + agg @ Wout[n]  (fp32 + split)
        mma_gemm<false, false, true, true, true><<<gridD, 256, SMEM>>>(
            aggh, aggl, wh + 655360 + 65536 + n * 16384,
            wl + 655360 + 65536 + n * 16384, nullptr, x, xh, xl, N, 64, 256);

        // FC block
        const __nv_bfloat16* W0h = wh + (size_t)(2 + 2 * n) * 65536;
        const __nv_bfloat16* W0l = wl + (size_t)(2 + 2 * n) * 65536;
        const __nv_bfloat16* W1h = wh + (size_t)(3 + 2 * n) * 65536;
        const __nv_bfloat16* W1l = wl + (size_t)(3 + 2 * n) * 65536;
        const float* b0 = fc_b + (size_t)n * 2 * 256;
        const float* b1 = b0 + 256;
        mma_gemm<true, true, false, false, true><<<gridD, 256, SMEM>>>(
            xh, xl, W0h, W0l, b0, nullptr, th, tl, N, 256, 256);
        mma_gemm<true, true, true, true, true><<<gridD, 256, SMEM>>>(
            th, tl, W1h, W1l, b1, x, xh, xl, N, 256, 256);
    }
}

// round 8
// speedup vs baseline: 1.0889x; 1.0889x over previous
#include <cuda_runtime.h>
#include <cuda_bf16.h>
#include <math.h>
#include <stdint.h>

#define NN 50000
#define EE 800000

// ---------------- scratch (no cudaMalloc allowed) ----------------
__device__ __align__(16) float g_tmp[NN * 256];
__device__ __align__(16) float g_v[NN * 64];
__device__ __align__(16) float g_agg[NN * 64];
__device__ __align__(16) float g_rbf[EE * 12];
// bf16 hi/lo transposed weights: 10x[256x256] + 8x[64x256 / 256x64]
__device__ __align__(16) __nv_bfloat16 g_wh[10 * 65536 + 8 * 16384];
__device__ __align__(16) __nv_bfloat16 g_wl[10 * 65536 + 8 * 16384];

__device__ __forceinline__ uint32_t smem_u32(const void* p) {
    uint32_t a;
    asm("{ .reg .u64 t; cvta.to.shared.u64 t, %1; cvt.u32.u64 %0, t; }" : "=r"(a) : "l"(p));
    return a;
}

__device__ __forceinline__ void ldsm4(uint32_t& r0, uint32_t& r1, uint32_t& r2,
                                      uint32_t& r3, uint32_t addr) {
    asm volatile("ldmatrix.sync.aligned.m8n8.x4.shared.b16 {%0,%1,%2,%3}, [%4];"
                 : "=r"(r0), "=r"(r1), "=r"(r2), "=r"(r3) : "r"(addr));
}

__device__ __forceinline__ void mma_bf16(float* c, const uint32_t* a, const uint32_t* b) {
    asm volatile(
        "mma.sync.aligned.m16n8k16.row.col.f32.bf16.bf16.f32 "
        "{%0,%1,%2,%3}, {%4,%5,%6,%7}, {%8,%9}, {%0,%1,%2,%3};"
        : "+f"(c[0]), "+f"(c[1]), "+f"(c[2]), "+f"(c[3])
        : "r"(a[0]), "r"(a[1]), "r"(a[2]), "r"(a[3]), "r"(b[0]), "r"(b[1]));
}

__device__ __forceinline__ float gelu_f(float x) {
    float x3 = x * x * x;
    float t = tanhf(0.7978845608028654f * (x + 0.044715f * x3));
    return 0.5f * x * (1.0f + t);
}

__device__ __forceinline__ void split_bf16(float v, __nv_bfloat16& h, __nv_bfloat16& l) {
    h = __float2bfloat16(v);
    l = __float2bfloat16(v - __bfloat162float(h));
}

// ---------------------------------------------------------------------------
// Weight convert: W [nm][K x N] fp32 -> out [nm][N x K] bf16 hi/lo (transposed)
// ---------------------------------------------------------------------------
__global__ void conv_w_kernel(const float* __restrict__ W,
                              __nv_bfloat16* __restrict__ oh,
                              __nv_bfloat16* __restrict__ ol,
                              int K, int Ncols, int total) {
    int idx = blockIdx.x * blockDim.x + threadIdx.x;
    if (idx >= total) return;
    int kn = K * Ncols;
    int m = idx / kn;
    int r = idx - m * kn;
    int n = r / K;
    int k = r - n * K;
    float w = W[(size_t)m * kn + (size_t)k * Ncols + n];
    split_bf16(w, oh[idx], ol[idx]);
}

// ---------------------------------------------------------------------------
// HMMA GEMM: fp32 A (in-kernel hi/lo split), pre-split bf16 W.
// BM=128, BN=64, BK=32, 256 threads, 8 warps (4m x 2n), warp tile 32x32.
// Double-buffered smem, register-prefetch LDG, ONE __syncthreads per chunk.
// 3-product split: Ah*Bh + Ah*Bl + Al*Bh, fp32 accumulate.
// ---------------------------------------------------------------------------
template <bool BIAS, bool GELU, bool RESID>
__global__ void __launch_bounds__(256, 2) mma_gemm(
    const float* __restrict__ A,
    const __nv_bfloat16* __restrict__ Bh_g,
    const __nv_bfloat16* __restrict__ Bl_g,
    const float* __restrict__ bias,
    float* __restrict__ C,
    int rows, int K, int ncols)
{
    constexpr int BM = 128, BN = 64, BK = 32, LD = 40;
    // per-stage byte layout: AH[10240] AL[10240] BH[5120] BL[5120] = 30720
    constexpr int STG = 30720;
    constexpr int OAL = 10240, OBH = 20480, OBL = 25600;
    extern __shared__ char smem[];

    int tid = threadIdx.x;
    int lane = tid & 31;
    int wid = tid >> 5;
    int wm = wid & 3;
    int wn = wid >> 2;
    int r0 = blockIdx.y * BM;
    int c0 = blockIdx.x * BN;

    uint32_t sb = smem_u32(smem);

    float acc[2][4][4];
#pragma unroll
    for (int i = 0; i < 2; i++)
#pragma unroll
        for (int j = 0; j < 4; j++)
#pragma unroll
            for (int k = 0; k < 4; k++) acc[i][j][k] = 0.f;

    int a_r = lane & 15;
    int a_c = (lane >> 4) * 8;
    int b_n = ((lane >> 4) * 8) + (lane & 7);
    int b_k = ((lane >> 3) & 1) * 8;

    // per-thread load mapping
    int ac4 = tid & 7;             // float4 index within 32-float A row
    int arr = tid >> 3;            // 0..31 base row
    int brow = tid >> 2;           // B row (0..63)
    int bc16 = tid & 3;

    float4 pa[4];
    uint4 pb_h, pb_l;

    auto ldg_chunk = [&](int kc) {
        int k0 = kc * BK;
#pragma unroll
        for (int q = 0; q < 4; q++) {
            int gr = r0 + arr + q * 32;
            pa[q] = (gr < rows)
                ? *reinterpret_cast<const float4*>(A + (size_t)gr * K + k0 + ac4 * 4)
                : make_float4(0.f, 0.f, 0.f, 0.f);
        }
        size_t ib = (size_t)(c0 + brow) * K + k0 + bc16 * 8;
        pb_h = *reinterpret_cast<const uint4*>(Bh_g + ib);
        pb_l = *reinterpret_cast<const uint4*>(Bl_g + ib);
    };

    auto sts_chunk = [&](int s) {
        uint32_t base = (uint32_t)s * STG;
#pragma unroll
        for (int q = 0; q < 4; q++) {
            int row = arr + q * 32;
            __nv_bfloat16 h0, h1, h2, h3, l0, l1, l2, l3;
            split_bf16(pa[q].x, h0, l0);
            split_bf16(pa[q].y, h1, l1);
            split_bf16(pa[q].z, h2, l2);
            split_bf16(pa[q].w, h3, l3);
            uint2 uh = make_uint2(
                ((uint32_t)__bfloat16_as_ushort(h1) << 16) | __bfloat16_as_ushort(h0),
                ((uint32_t)__bfloat16_as_ushort(h3) << 16) | __bfloat16_as_ushort(h2));
            uint2 ul = make_uint2(
                ((uint32_t)__bfloat16_as_ushort(l1) << 16) | __bfloat16_as_ushort(l0),
                ((uint32_t)__bfloat16_as_ushort(l3) << 16) | __bfloat16_as_ushort(l2));
            uint32_t d = base + (uint32_t)((row * LD + ac4 * 4) * 2);
            *reinterpret_cast<uint2*>(smem + d) = uh;
            *reinterpret_cast<uint2*>(smem + OAL + d) = ul;
        }
        uint32_t db = base + (uint32_t)((brow * LD + bc16 * 8) * 2);
        *reinterpret_cast<uint4*>(smem + OBH + db) = pb_h;
        *reinterpret_cast<uint4*>(smem + OBL + db) = pb_l;
    };

    int nkc = K / BK;
    ldg_chunk(0);
    sts_chunk(0);
    __syncthreads();

    for (int kc = 0; kc < nkc; kc++) {
        int s = kc & 1;
        if (kc + 1 < nkc) ldg_chunk(kc + 1);   // LDG overlaps HMMA below

        uint32_t aHb = sb + (uint32_t)s * STG;
        uint32_t aLb = aHb + OAL;
        uint32_t bHb = aHb + OBH;
        uint32_t bLb = aHb + OBL;
#pragma unroll
        for (int kk = 0; kk < 2; kk++) {
            uint32_t ah[2][4], al[2][4], bh[2][4], bl[2][4];
#pragma unroll
            for (int im = 0; im < 2; im++) {
                uint32_t off = (uint32_t)(((wm * 32 + im * 16 + a_r) * LD + kk * 16 + a_c) * 2);
                ldsm4(ah[im][0], ah[im][1], ah[im][2], ah[im][3], aHb + off);
                ldsm4(al[im][0], al[im][1], al[im][2], al[im][3], aLb + off);
            }
#pragma unroll
            for (int jp = 0; jp < 2; jp++) {
                uint32_t off = (uint32_t)(((wn * 32 + jp * 16 + b_n) * LD + kk * 16 + b_k) * 2);
                ldsm4(bh[jp][0], bh[jp][1], bh[jp][2], bh[jp][3], bHb + off);
                ldsm4(bl[jp][0], bl[jp][1], bl[jp][2], bl[jp][3], bLb + off);
            }
#pragma unroll
            for (int im = 0; im < 2; im++)
#pragma unroll
                for (int jn = 0; jn < 4; jn++) {
                    const uint32_t* pbh = &bh[jn >> 1][(jn & 1) * 2];
                    const uint32_t* pbl = &bl[jn >> 1][(jn & 1) * 2];
                    mma_bf16(acc[im][jn], ah[im], pbh);
                    mma_bf16(acc[im][jn], ah[im], pbl);
                    mma_bf16(acc[im][jn], al[im], pbh);
                }
        }
        if (kc + 1 < nkc) sts_chunk(s ^ 1);
        __syncthreads();
    }

    // --- epilogue ---
#pragma unroll
    for (int im = 0; im < 2; im++) {
        int rowa = r0 + wm * 32 + im * 16 + (lane >> 2);
#pragma unroll
        for (int jn = 0; jn < 4; jn++) {
            int col = c0 + wn * 32 + jn * 8 + (lane & 3) * 2;
            float2 bv = make_float2(0.f, 0.f);
            if (BIAS) bv = *reinterpret_cast<const float2*>(bias + col);
#pragma unroll
            for (int h = 0; h < 2; h++) {
                int row = rowa + h * 8;
                if (row >= rows) continue;
                float vx = acc[im][jn][h * 2 + 0];
                float vy = acc[im][jn][h * 2 + 1];
                if (BIAS) { vx += bv.x; vy += bv.y; }
                if (GELU) { vx = gelu_f(vx); vy = gelu_f(vy); }
                float* p = C + (size_t)row * ncols + col;
                if (RESID) {
                    float2 old = *reinterpret_cast<const float2*>(p);
                    vx += old.x; vy += old.y;
                }
                *reinterpret_cast<float2*>(p) = make_float2(vx, vy);
            }
        }
    }
}

// ---------------------------------------------------------------------------
// Embedding init
// ---------------------------------------------------------------------------
__global__ void embed_kernel(const int* __restrict__ z,
                             const float* __restrict__ table,
                             const float* __restrict__ W,
                             const float* __restrict__ b,
                             float* __restrict__ x, int N) {
    int n = blockIdx.x;
    if (n >= N) return;
    int d = threadIdx.x;
    int t = z[n];
    float acc = b[d];
#pragma unroll
    for (int h = 0; h < 5; h++) acc += table[t * 5 + h] * W[h * 256 + d];
    x[(size_t)n * 256 + d] = acc;
}

// ---------------------------------------------------------------------------
// Bessel RBF with polynomial envelope (p=5)
// ---------------------------------------------------------------------------
__global__ void rbf_kernel(const int* __restrict__ ei,
                           const float* __restrict__ pos,
                           const float* __restrict__ freqs,
                           int E) {
    int e = blockIdx.x * blockDim.x + threadIdx.x;
    if (e >= E) return;
    int i = ei[e];
    int j = ei[E + e];
    float dx = pos[i * 3 + 0] - pos[j * 3 + 0];
    float dy = pos[i * 3 + 1] - pos[j * 3 + 1];
    float dz = pos[i * 3 + 2] - pos[j * 3 + 2];
    float dist = sqrtf(dx * dx + dy * dy + dz * dz + 1e-12f);
    float x = dist * 0.2f;
    float x2 = x * x;
    float x4 = x2 * x2;
    float env = 1.0f / x + (-21.0f) * x4 + 35.0f * x4 * x + (-15.0f) * x4 * x2;
#pragma unroll
    for (int r = 0; r < 12; r++)
        g_rbf[(size_t)e * 12 + r] = env * sinf(freqs[r] * x);
}

// ---------------------------------------------------------------------------
// Edge messages + scatter: 16 threads/edge, vector red.global.add.v4.f32
// ---------------------------------------------------------------------------
__global__ void edge_msg_kernel(const int* __restrict__ ei,
                                const float* __restrict__ Wrbf,  // [12,64]
                                int E) {
    __shared__ float sW[12 * 64];
    for (int t = threadIdx.x; t < 12 * 64; t += blockDim.x) sW[t] = Wrbf[t];
    __syncthreads();

    int gt = blockIdx.x * blockDim.x + threadIdx.x;
    int e = gt >> 4;
    if (e >= E) return;
    int sub = gt & 15;
    int m0 = sub * 4;

    int i = ei[e];
    int j = ei[E + e];

    float gx = 0.f, gy = 0.f, gz = 0.f, gw = 0.f;
#pragma unroll
    for (int r = 0; r < 12; r++) {
        float rv = __ldg(&g_rbf[(size_t)e * 12 + r]);
        const float* w = &sW[r * 64 + m0];
        gx = fmaf(rv, w[0], gx);
        gy = fmaf(rv, w[1], gy);
        gz = fmaf(rv, w[2], gz);
        gw = fmaf(rv, w[3], gw);
    }
    const float4 vj = *reinterpret_cast<const float4*>(g_v + (size_t)j * 64 + m0);
    float vx = vj.x * gx, vy = vj.y * gy, vz = vj.z * gz, vw = vj.w * gw;
    float* dst = g_agg + (size_t)i * 64 + m0;
    asm volatile("red.global.add.v4.f32 [%0], {%1, %2, %3, %4};"
                 :: "l"(dst), "f"(vx), "f"(vy), "f"(vz), "f"(vw) : "memory");
}

// ---------------------------------------------------------------------------
// Launcher
// ---------------------------------------------------------------------------
extern "C" void kernel_launch(void* const* d_in, const int* in_sizes, int n_in,
                              void* d_out, int out_size) {
    const int* z = (const int*)d_in[0];
    const float* pos = (const float*)d_in[1];
    const int* ei = (const int*)d_in[4];
    const float* emb_table = (const float*)d_in[5];
    const float* emb_W = (const float*)d_in[6];
    const float* emb_b = (const float*)d_in[7];
    const float* freqs = (const float*)d_in[8];
    const float* fc0_W = (const float*)d_in[9];
    const float* fc0_b = (const float*)d_in[10];
    const float* conv_Wv = (const float*)d_in[11];
    const float* conv_Wrbf = (const float*)d_in[12];
    const float* conv_Wout = (const float*)d_in[13];
    const float* fc_W = (const float*)d_in[14];
    const float* fc_b = (const float*)d_in[15];

    int N = in_sizes[1] / 3;   // 50000
    int E = in_sizes[4] / 2;   // 800000

    float* x = (float*)d_out;

    float *tmp, *vbuf, *agg;
    __nv_bfloat16 *wh, *wl;
    cudaGetSymbolAddress((void**)&tmp, g_tmp);
    cudaGetSymbolAddress((void**)&vbuf, g_v);
    cudaGetSymbolAddress((void**)&agg, g_agg);
    cudaGetSymbolAddress((void**)&wh, g_wh);
    cudaGetSymbolAddress((void**)&wl, g_wl);

    const int SMEM = 2 * 30720;  // 61440
    cudaFuncSetAttribute((const void*)mma_gemm<true, true, false>,
                         cudaFuncAttributeMaxDynamicSharedMemorySize, SMEM);
    cudaFuncSetAttribute((const void*)mma_gemm<true, true, true>,
                         cudaFuncAttributeMaxDynamicSharedMemorySize, SMEM);
    cudaFuncSetAttribute((const void*)mma_gemm<false, false, false>,
                         cudaFuncAttributeMaxDynamicSharedMemorySize, SMEM);
    cudaFuncSetAttribute((const void*)mma_gemm<false, false, true>,
                         cudaFuncAttributeMaxDynamicSharedMemorySize, SMEM);

    // ---- weight conversion (hi/lo bf16, transposed) ----
    {
        int T = 2 * 65536;
        conv_w_kernel<<<(T + 255) / 256, 256>>>(fc0_W, wh, wl, 256, 256, T);
        T = 8 * 65536;
        conv_w_kernel<<<(T + 255) / 256, 256>>>(fc_W, wh + 2 * 65536, wl + 2 * 65536, 256, 256, T);
        T = 4 * 16384;
        conv_w_kernel<<<(T + 255) / 256, 256>>>(conv_Wv, wh + 655360, wl + 655360, 256, 64, T);
        conv_w_kernel<<<(T + 255) / 256, 256>>>(conv_Wout, wh + 655360 + 65536,
                                                wl + 655360 + 65536, 64, 256, T);
    }

    dim3 gridD(4, (N + 127) / 128);   // ncols=256
    dim3 gridM(1, (N + 127) / 128);   // ncols=64

    // 1. init embedding
    embed_kernel<<<N, 256>>>(z, emb_table, emb_W, emb_b, x, N);

    // 2. init FC block
    mma_gemm<true, true, false><<<gridD, 256, SMEM>>>(x, wh, wl, fc0_b, tmp, N, 256, 256);
    mma_gemm<true, true, false><<<gridD, 256, SMEM>>>(tmp, wh + 65536, wl + 65536,
                                                      fc0_b + 256, x, N, 256, 256);

    // 3. radial basis
    rbf_kernel<<<(E + 255) / 256, 256>>>(ei, pos, freqs, E);

    // 4. interaction blocks
    for (int n = 0; n < 4; n++) {
        cudaMemsetAsync(agg, 0, (size_t)N * 64 * sizeof(float));

        // v = x @ Wv[n]
        mma_gemm<false, false, false><<<gridM, 256, SMEM>>>(
            x, wh + 655360 + n * 16384, wl + 655360 + n * 16384, nullptr,
            vbuf, N, 256, 64);

        // gated messages + vector-red scatter
        edge_msg_kernel<<<(E * 16 + 255) / 256, 256>>>(
            ei, conv_Wrbf + (size_t)n * 12 * 64, E);

        // x = x + agg @ Wout[n]
        mma_gemm<false, false, true><<<gridD, 256, SMEM>>>(
            agg, wh + 655360 + 65536 + n * 16384, wl + 655360 + 65536 + n * 16384,
            nullptr, x, N, 64, 256);

        // FC block
        const __nv_bfloat16* W0h = wh + (size_t)(2 + 2 * n) * 65536;
        const __nv_bfloat16* W0l = wl + (size_t)(2 + 2 * n) * 65536;
        const __nv_bfloat16* W1h = wh + (size_t)(3 + 2 * n) * 65536;
        const __nv_bfloat16* W1l = wl + (size_t)(3 + 2 * n) * 65536;
        const float* b0 = fc_b + (size_t)n * 2 * 256;
        const float* b1 = b0 + 256;
        mma_gemm<true, true, false><<<gridD, 256, SMEM>>>(x, W0h, W0l, b0, tmp, N, 256, 256);
        mma_gemm<true, true, true><<<gridD, 256, SMEM>>>(tmp, W1h, W1l, b1, x, N, 256, 256);
    }
}

// round 9
// speedup vs baseline: 1.0934x; 1.0041x over previous
#include <cuda_runtime.h>
#include <cuda_bf16.h>
#include <math.h>
#include <stdint.h>

#define NN 50000
#define EE 800000

// ---------------- scratch (no cudaMalloc allowed) ----------------
__device__ __align__(16) float g_tmp[NN * 256];
__device__ __align__(16) float g_v[NN * 64];
__device__ __align__(16) float g_agg[NN * 64];
__device__ __align__(16) float g_rbf[EE * 12];   // CSR-sorted order
// CSR structures
__device__ int g_cnt[NN];
__device__ int g_off[NN + 1];
__device__ int g_work[NN];
__device__ int g_ej[EE];    // sorted: source node j per slot
__device__ int g_si[EE];    // sorted: dest node i per slot
__device__ int g_perm[EE];  // slot -> original edge
// bf16 hi/lo transposed weights: 10x[256x256] + 8x[64x256 / 256x64]
__device__ __align__(16) __nv_bfloat16 g_wh[10 * 65536 + 8 * 16384];
__device__ __align__(16) __nv_bfloat16 g_wl[10 * 65536 + 8 * 16384];

__device__ __forceinline__ uint32_t smem_u32(const void* p) {
    uint32_t a;
    asm("{ .reg .u64 t; cvta.to.shared.u64 t, %1; cvt.u32.u64 %0, t; }" : "=r"(a) : "l"(p));
    return a;
}

__device__ __forceinline__ void ldsm4(uint32_t& r0, uint32_t& r1, uint32_t& r2,
                                      uint32_t& r3, uint32_t addr) {
    asm volatile("ldmatrix.sync.aligned.m8n8.x4.shared.b16 {%0,%1,%2,%3}, [%4];"
                 : "=r"(r0), "=r"(r1), "=r"(r2), "=r"(r3) : "r"(addr));
}

__device__ __forceinline__ void mma_bf16(float* c, const uint32_t* a, const uint32_t* b) {
    asm volatile(
        "mma.sync.aligned.m16n8k16.row.col.f32.bf16.bf16.f32 "
        "{%0,%1,%2,%3}, {%4,%5,%6,%7}, {%8,%9}, {%0,%1,%2,%3};"
        : "+f"(c[0]), "+f"(c[1]), "+f"(c[2]), "+f"(c[3])
        : "r"(a[0]), "r"(a[1]), "r"(a[2]), "r"(a[3]), "r"(b[0]), "r"(b[1]));
}

__device__ __forceinline__ float gelu_f(float x) {
    float x3 = x * x * x;
    float t = tanhf(0.7978845608028654f * (x + 0.044715f * x3));
    return 0.5f * x * (1.0f + t);
}

__device__ __forceinline__ void split_bf16(float v, __nv_bfloat16& h, __nv_bfloat16& l) {
    h = __float2bfloat16(v);
    l = __float2bfloat16(v - __bfloat162float(h));
}

// ---------------------------------------------------------------------------
// Weight convert: W [nm][K x N] fp32 -> out [nm][N x K] bf16 hi/lo (transposed)
// ---------------------------------------------------------------------------
__global__ void conv_w_kernel(const float* __restrict__ W,
                              __nv_bfloat16* __restrict__ oh,
                              __nv_bfloat16* __restrict__ ol,
                              int K, int Ncols, int total) {
    int idx = blockIdx.x * blockDim.x + threadIdx.x;
    if (idx >= total) return;
    int kn = K * Ncols;
    int m = idx / kn;
    int r = idx - m * kn;
    int n = r / K;
    int k = r - n * K;
    float w = W[(size_t)m * kn + (size_t)k * Ncols + n];
    split_bf16(w, oh[idx], ol[idx]);
}

// ---------------------------------------------------------------------------
// HMMA GEMM (R3 version, verbatim): CTA tile 128x64, BK=32, 8 warps.
// 3-product split: Ah*Bh + Ah*Bl + Al*Bh, fp32 accumulate.
// ---------------------------------------------------------------------------
template <bool BIAS, bool GELU, bool RESID>
__global__ void __launch_bounds__(256) mma_gemm(
    const float* __restrict__ A,
    const __nv_bfloat16* __restrict__ Bh_g,
    const __nv_bfloat16* __restrict__ Bl_g,
    const float* __restrict__ bias,
    float* __restrict__ C,
    int rows, int K, int ncols)
{
    constexpr int BM = 128, BN = 64, BK = 32, LD = 40;
    __shared__ __nv_bfloat16 sAh[BM * LD];
    __shared__ __nv_bfloat16 sAl[BM * LD];
    __shared__ __nv_bfloat16 sBh[BN * LD];
    __shared__ __nv_bfloat16 sBl[BN * LD];

    int tid = threadIdx.x;
    int lane = tid & 31;
    int wid = tid >> 5;
    int wm = wid & 3;
    int wn = wid >> 2;
    int r0 = blockIdx.y * BM;
    int c0 = blockIdx.x * BN;

    float acc[2][4][4];
#pragma unroll
    for (int i = 0; i < 2; i++)
#pragma unroll
        for (int j = 0; j < 4; j++)
#pragma unroll
            for (int k = 0; k < 4; k++) acc[i][j][k] = 0.f;

    uint32_t aH = smem_u32(sAh), aL = smem_u32(sAl);
    uint32_t bH = smem_u32(sBh), bL = smem_u32(sBl);

    int a_r = lane & 15;
    int a_c = (lane >> 4) * 8;
    int b_n = ((lane >> 4) * 8) + (lane & 7);
    int b_k = ((lane >> 3) & 1) * 8;

    int nkc = K / BK;
    for (int kc = 0; kc < nkc; kc++) {
        int k0 = kc * BK;
        {
            int c4 = tid & 7;
            int rr = tid >> 3;
#pragma unroll
            for (int q = 0; q < 4; q++) {
                int row = rr + q * 32;
                int gr = r0 + row;
                float4 a = make_float4(0.f, 0.f, 0.f, 0.f);
                if (gr < rows)
                    a = *reinterpret_cast<const float4*>(A + (size_t)gr * K + k0 + c4 * 4);
                __nv_bfloat16 h0, h1, h2, h3, l0, l1, l2, l3;
                split_bf16(a.x, h0, l0);
                split_bf16(a.y, h1, l1);
                split_bf16(a.z, h2, l2);
                split_bf16(a.w, h3, l3);
                uint2 uh = make_uint2(
                    ((uint32_t)__bfloat16_as_ushort(h1) << 16) | __bfloat16_as_ushort(h0),
                    ((uint32_t)__bfloat16_as_ushort(h3) << 16) | __bfloat16_as_ushort(h2));
                uint2 ul = make_uint2(
                    ((uint32_t)__bfloat16_as_ushort(l1) << 16) | __bfloat16_as_ushort(l0),
                    ((uint32_t)__bfloat16_as_ushort(l3) << 16) | __bfloat16_as_ushort(l2));
                *reinterpret_cast<uint2*>(sAh + row * LD + c4 * 4) = uh;
                *reinterpret_cast<uint2*>(sAl + row * LD + c4 * 4) = ul;
            }
        }
        {
            int rowb = tid >> 2;
            int c8 = tid & 3;
            size_t g = (size_t)(c0 + rowb) * K + k0 + c8 * 8;
            *reinterpret_cast<uint4*>(sBh + rowb * LD + c8 * 8) =
                *reinterpret_cast<const uint4*>(Bh_g + g);
            *reinterpret_cast<uint4*>(sBl + rowb * LD + c8 * 8) =
                *reinterpret_cast<const uint4*>(Bl_g + g);
        }
        __syncthreads();

#pragma unroll
        for (int kk = 0; kk < 2; kk++) {
            uint32_t ah[2][4], al[2][4], bh[2][4], bl[2][4];
#pragma unroll
            for (int im = 0; im < 2; im++) {
                uint32_t off = (uint32_t)(((wm * 32 + im * 16 + a_r) * LD + kk * 16 + a_c) * 2);
                ldsm4(ah[im][0], ah[im][1], ah[im][2], ah[im][3], aH + off);
                ldsm4(al[im][0], al[im][1], al[im][2], al[im][3], aL + off);
            }
#pragma unroll
            for (int jp = 0; jp < 2; jp++) {
                uint32_t off = (uint32_t)(((wn * 32 + jp * 16 + b_n) * LD + kk * 16 + b_k) * 2);
                ldsm4(bh[jp][0], bh[jp][1], bh[jp][2], bh[jp][3], bH + off);
                ldsm4(bl[jp][0], bl[jp][1], bl[jp][2], bl[jp][3], bL + off);
            }
#pragma unroll
            for (int im = 0; im < 2; im++)
#pragma unroll
                for (int jn = 0; jn < 4; jn++) {
                    const uint32_t* pbh = &bh[jn >> 1][(jn & 1) * 2];
                    const uint32_t* pbl = &bl[jn >> 1][(jn & 1) * 2];
                    mma_bf16(acc[im][jn], ah[im], pbh);
                    mma_bf16(acc[im][jn], ah[im], pbl);
                    mma_bf16(acc[im][jn], al[im], pbh);
                }
        }
        __syncthreads();
    }

#pragma unroll
    for (int im = 0; im < 2; im++) {
        int rowa = r0 + wm * 32 + im * 16 + (lane >> 2);
        int rowb2 = rowa + 8;
#pragma unroll
        for (int jn = 0; jn < 4; jn++) {
            int col = c0 + wn * 32 + jn * 8 + (lane & 3) * 2;
            float2 bv = make_float2(0.f, 0.f);
            if (BIAS) bv = *reinterpret_cast<const float2*>(bias + col);
#pragma unroll
            for (int h = 0; h < 2; h++) {
                int row = h ? rowb2 : rowa;
                if (row >= rows) continue;
                float vx = acc[im][jn][h * 2 + 0];
                float vy = acc[im][jn][h * 2 + 1];
                if (BIAS) { vx += bv.x; vy += bv.y; }
                if (GELU) { vx = gelu_f(vx); vy = gelu_f(vy); }
                float* p = C + (size_t)row * ncols + col;
                if (RESID) {
                    float2 old = *reinterpret_cast<const float2*>(p);
                    vx += old.x; vy += old.y;
                }
                *reinterpret_cast<float2*>(p) = make_float2(vx, vy);
            }
        }
    }
}

// ---------------------------------------------------------------------------
// Embedding init
// ---------------------------------------------------------------------------
__global__ void embed_kernel(const int* __restrict__ z,
                             const float* __restrict__ table,
                             const float* __restrict__ W,
                             const float* __restrict__ b,
                             float* __restrict__ x, int N) {
    int n = blockIdx.x;
    if (n >= N) return;
    int d = threadIdx.x;
    int t = z[n];
    float acc = b[d];
#pragma unroll
    for (int h = 0; h < 5; h++) acc += table[t * 5 + h] * W[h * 256 + d];
    x[(size_t)n * 256 + d] = acc;
}

// ---------------------------------------------------------------------------
// CSR build: histogram -> scan -> scatter (fills g_ej, g_si, g_perm)
// ---------------------------------------------------------------------------
__global__ void hist_kernel(const int* __restrict__ ei, int E) {
    int e = blockIdx.x * blockDim.x + threadIdx.x;
    if (e >= E) return;
    atomicAdd(&g_cnt[ei[e]], 1);
}

__global__ void scan_kernel(int N) {
    __shared__ int ssum[1024];
    int t = threadIdx.x;
    int C = (N + 1023) / 1024;
    int lo = t * C;
    int hi = min(N, lo + C);
    int s = 0;
    for (int k = lo; k < hi; k++) s += g_cnt[k];
    ssum[t] = s;
    __syncthreads();
    for (int d = 1; d < 1024; d <<= 1) {
        int v = (t >= d) ? ssum[t - d] : 0;
        __syncthreads();
        ssum[t] += v;
        __syncthreads();
    }
    int pre = (t == 0) ? 0 : ssum[t - 1];
    for (int k = lo; k < hi; k++) {
        g_off[k] = pre;
        g_work[k] = pre;
        pre += g_cnt[k];
    }
    if (t == 1023) g_off[N] = ssum[1023];
}

__global__ void scatter_kernel(const int* __restrict__ ei, int E) {
    int e = blockIdx.x * blockDim.x + threadIdx.x;
    if (e >= E) return;
    int i = ei[e];
    int pos = atomicAdd(&g_work[i], 1);
    g_ej[pos] = ei[E + e];
    g_si[pos] = i;
    g_perm[pos] = e;
}

// ---------------------------------------------------------------------------
// RBF in CSR-sorted order, sin recurrence: sin(k f) via Chebyshev
// ---------------------------------------------------------------------------
__global__ void rbf_sorted_kernel(const int* __restrict__ ei,
                                  const float* __restrict__ pos,
                                  const float* __restrict__ freqs,
                                  int E) {
    int p = blockIdx.x * blockDim.x + threadIdx.x;
    if (p >= E) return;
    int e = g_perm[p];
    int i = ei[e];
    int j = ei[E + e];
    float dx = pos[i * 3 + 0] - pos[j * 3 + 0];
    float dy = pos[i * 3 + 1] - pos[j * 3 + 1];
    float dz = pos[i * 3 + 2] - pos[j * 3 + 2];
    float dist = sqrtf(dx * dx + dy * dy + dz * dz + 1e-12f);
    float x = dist * 0.2f;
    float x2 = x * x;
    float x4 = x2 * x2;
    float env = 1.0f / x + (-21.0f) * x4 + 35.0f * x4 * x + (-15.0f) * x4 * x2;

    float f = freqs[0] * x;          // pi*x
    float s1, c1;
    sincosf(f, &s1, &c1);
    float twoc = 2.0f * c1;
    float sprev = 0.f, scur = s1;
    float* out = g_rbf + (size_t)p * 12;
#pragma unroll
    for (int r = 0; r < 12; r++) {
        out[r] = env * scur;
        float snext = twoc * scur - sprev;
        sprev = scur;
        scur = snext;
    }
}

// ---------------------------------------------------------------------------
// Segmented edge aggregation: warp owns 32 consecutive CSR slots (sorted by
// dest i). Lanes span m-columns (2 each). Flush running sum via red.add only
// at destination boundaries (~2-3 per chunk).
// ---------------------------------------------------------------------------
__global__ void edge_seg_kernel(const float* __restrict__ Wrbf, int E) {
    __shared__ float sW[12 * 64];
    for (int t = threadIdx.x; t < 12 * 64; t += blockDim.x) sW[t] = Wrbf[t];
    __syncthreads();

    int chunk = blockIdx.x * (blockDim.x >> 5) + (threadIdx.x >> 5);
    int lane = threadIdx.x & 31;
    int p0 = chunk * 32;
    if (p0 >= E) return;
    int p1 = min(p0 + 32, E);

    float a0 = 0.f, a1 = 0.f;
    int icur = g_si[p0];
    for (int p = p0; p < p1; p++) {
        int j = g_ej[p];
        const float4* rp = reinterpret_cast<const float4*>(g_rbf + (size_t)p * 12);
        float4 f0 = __ldg(rp);
        float4 f1 = __ldg(rp + 1);
        float4 f2 = __ldg(rp + 2);
        float r[12] = {f0.x, f0.y, f0.z, f0.w, f1.x, f1.y, f1.z, f1.w,
                       f2.x, f2.y, f2.z, f2.w};
        float gg0 = 0.f, gg1 = 0.f;
#pragma unroll
        for (int rr = 0; rr < 12; rr++) {
            gg0 = fmaf(r[rr], sW[rr * 64 + lane], gg0);
            gg1 = fmaf(r[rr], sW[rr * 64 + 32 + lane], gg1);
        }
        a0 = fmaf(__ldg(g_v + (size_t)j * 64 + lane), gg0, a0);
        a1 = fmaf(__ldg(g_v + (size_t)j * 64 + 32 + lane), gg1, a1);

        int inext = (p + 1 < E) ? g_si[p + 1] : -1;
        bool flush = (p == p1 - 1) || (inext != icur);
        if (flush) {
            float* d0 = g_agg + (size_t)icur * 64 + lane;
            float* d1 = d0 + 32;
            asm volatile("red.global.add.f32 [%0], %1;" :: "l"(d0), "f"(a0) : "memory");
            asm volatile("red.global.add.f32 [%0], %1;" :: "l"(d1), "f"(a1) : "memory");
            a0 = 0.f; a1 = 0.f;
            icur = inext;
        }
    }
}

// ---------------------------------------------------------------------------
// Launcher
// ---------------------------------------------------------------------------
extern "C" void kernel_launch(void* const* d_in, const int* in_sizes, int n_in,
                              void* d_out, int out_size) {
    const int* z = (const int*)d_in[0];
    const float* pos = (const float*)d_in[1];
    const int* ei = (const int*)d_in[4];
    const float* emb_table = (const float*)d_in[5];
    const float* emb_W = (const float*)d_in[6];
    const float* emb_b = (const float*)d_in[7];
    const float* freqs = (const float*)d_in[8];
    const float* fc0_W = (const float*)d_in[9];
    const float* fc0_b = (const float*)d_in[10];
    const float* conv_Wv = (const float*)d_in[11];
    const float* conv_Wrbf = (const float*)d_in[12];
    const float* conv_Wout = (const float*)d_in[13];
    const float* fc_W = (const float*)d_in[14];
    const float* fc_b = (const float*)d_in[15];

    int N = in_sizes[1] / 3;   // 50000
    int E = in_sizes[4] / 2;   // 800000

    float* x = (float*)d_out;

    float *tmp, *vbuf, *agg;
    int* cnt;
    __nv_bfloat16 *wh, *wl;
    cudaGetSymbolAddress((void**)&tmp, g_tmp);
    cudaGetSymbolAddress((void**)&vbuf, g_v);
    cudaGetSymbolAddress((void**)&agg, g_agg);
    cudaGetSymbolAddress((void**)&cnt, g_cnt);
    cudaGetSymbolAddress((void**)&wh, g_wh);
    cudaGetSymbolAddress((void**)&wl, g_wl);

    // ---- weight conversion (hi/lo bf16, transposed) ----
    {
        int T = 2 * 65536;
        conv_w_kernel<<<(T + 255) / 256, 256>>>(fc0_W, wh, wl, 256, 256, T);
        T = 8 * 65536;
        conv_w_kernel<<<(T + 255) / 256, 256>>>(fc_W, wh + 2 * 65536, wl + 2 * 65536, 256, 256, T);
        T = 4 * 16384;
        conv_w_kernel<<<(T + 255) / 256, 256>>>(conv_Wv, wh + 655360, wl + 655360, 256, 64, T);
        conv_w_kernel<<<(T + 255) / 256, 256>>>(conv_Wout, wh + 655360 + 65536,
                                                wl + 655360 + 65536, 64, 256, T);
    }

    // ---- CSR build + sorted rbf ----
    cudaMemsetAsync(cnt, 0, N * sizeof(int));
    hist_kernel<<<(E + 255) / 256, 256>>>(ei, E);
    scan_kernel<<<1, 1024>>>(N);
    scatter_kernel<<<(E + 255) / 256, 256>>>(ei, E);
    rbf_sorted_kernel<<<(E + 255) / 256, 256>>>(ei, pos, freqs, E);

    dim3 gridD(4, (N + 127) / 128);   // ncols=256
    dim3 gridM(1, (N + 127) / 128);   // ncols=64
    int nchunks = (E + 31) / 32;
    int segBlocks = (nchunks + 7) / 8;

    // 1. init embedding
    embed_kernel<<<N, 256>>>(z, emb_table, emb_W, emb_b, x, N);

    // 2. init FC block
    mma_gemm<true, true, false><<<gridD, 256>>>(x, wh, wl, fc0_b, tmp, N, 256, 256);
    mma_gemm<true, true, false><<<gridD, 256>>>(tmp, wh + 65536, wl + 65536,
                                                fc0_b + 256, x, N, 256, 256);

    // 3. interaction blocks
    for (int n = 0; n < 4; n++) {
        cudaMemsetAsync(agg, 0, (size_t)N * 64 * sizeof(float));

        // v = x @ Wv[n]
        mma_gemm<false, false, false><<<gridM, 256>>>(
            x, wh + 655360 + n * 16384, wl + 655360 + n * 16384, nullptr,
            vbuf, N, 256, 64);

        // segmented gather-scatter over CSR-sorted edges
        edge_seg_kernel<<<segBlocks, 256>>>(conv_Wrbf + (size_t)n * 12 * 64, E);

        // x = x + agg @ Wout[n]
        mma_gemm<false, false, true><<<gridD, 256>>>(
            agg, wh + 655360 + 65536 + n * 16384, wl + 655360 + 65536 + n * 16384,
            nullptr, x, N, 64, 256);

        // FC block
        const __nv_bfloat16* W0h = wh + (size_t)(2 + 2 * n) * 65536;
        const __nv_bfloat16* W0l = wl + (size_t)(2 + 2 * n) * 65536;
        const __nv_bfloat16* W1h = wh + (size_t)(3 + 2 * n) * 65536;
        const __nv_bfloat16* W1l = wl + (size_t)(3 + 2 * n) * 65536;
        const float* b0 = fc_b + (size_t)n * 2 * 256;
        const float* b1 = b0 + 256;
        mma_gemm<true, true, false><<<gridD, 256>>>(x, W0h, W0l, b0, tmp, N, 256, 256);
        mma_gemm<true, true, true><<<gridD, 256>>>(tmp, W1h, W1l, b1, x, N, 256, 256);
    }
}

// round 10
// speedup vs baseline: 1.1026x; 1.0085x over previous
#include <cuda_runtime.h>
#include <cuda_bf16.h>
#include <math.h>
#include <stdint.h>

#define NN 50000
#define EE 800000

// ---------------- scratch (no cudaMalloc allowed) ----------------
__device__ __align__(16) float g_tmp[NN * 256];
__device__ __align__(16) float g_v[NN * 64];
__device__ __align__(16) float g_agg[NN * 64];
__device__ __align__(16) float g_rbf[EE * 12];
// bf16 hi/lo transposed weights: 10x[256x256] + 8x[64x256 / 256x64]
__device__ __align__(16) __nv_bfloat16 g_wh[10 * 65536 + 8 * 16384];
__device__ __align__(16) __nv_bfloat16 g_wl[10 * 65536 + 8 * 16384];

__device__ __forceinline__ uint32_t smem_u32(const void* p) {
    uint32_t a;
    asm("{ .reg .u64 t; cvta.to.shared.u64 t, %1; cvt.u32.u64 %0, t; }" : "=r"(a) : "l"(p));
    return a;
}

__device__ __forceinline__ void ldsm4(uint32_t& r0, uint32_t& r1, uint32_t& r2,
                                      uint32_t& r3, uint32_t addr) {
    asm volatile("ldmatrix.sync.aligned.m8n8.x4.shared.b16 {%0,%1,%2,%3}, [%4];"
                 : "=r"(r0), "=r"(r1), "=r"(r2), "=r"(r3) : "r"(addr));
}

__device__ __forceinline__ void mma_bf16(float* c, const uint32_t* a, const uint32_t* b) {
    asm volatile(
        "mma.sync.aligned.m16n8k16.row.col.f32.bf16.bf16.f32 "
        "{%0,%1,%2,%3}, {%4,%5,%6,%7}, {%8,%9}, {%0,%1,%2,%3};"
        : "+f"(c[0]), "+f"(c[1]), "+f"(c[2]), "+f"(c[3])
        : "r"(a[0]), "r"(a[1]), "r"(a[2]), "r"(a[3]), "r"(b[0]), "r"(b[1]));
}

__device__ __forceinline__ float gelu_f(float x) {
    float x3 = x * x * x;
    float t = tanhf(0.7978845608028654f * (x + 0.044715f * x3));
    return 0.5f * x * (1.0f + t);
}

__device__ __forceinline__ void split_bf16(float v, __nv_bfloat16& h, __nv_bfloat16& l) {
    h = __float2bfloat16(v);
    l = __float2bfloat16(v - __bfloat162float(h));
}

// ---------------------------------------------------------------------------
// Weight convert: W [nm][K x N] fp32 -> out [nm][N x K] bf16 hi/lo (transposed)
// ---------------------------------------------------------------------------
__global__ void conv_w_kernel(const float* __restrict__ W,
                              __nv_bfloat16* __restrict__ oh,
                              __nv_bfloat16* __restrict__ ol,
                              int K, int Ncols, int total) {
    int idx = blockIdx.x * blockDim.x + threadIdx.x;
    if (idx >= total) return;
    int kn = K * Ncols;
    int m = idx / kn;
    int r = idx - m * kn;
    int n = r / K;
    int k = r - n * K;
    float w = W[(size_t)m * kn + (size_t)k * Ncols + n];
    split_bf16(w, oh[idx], ol[idx]);
}

// ---------------------------------------------------------------------------
// HMMA GEMM: BM=128, templated BN (64 or 128), BK=32, 256 threads, 8 warps
// (4m x 2n), warp tile 32 x (BN/2). 3-product bf16 split, fp32 accumulate.
// BN=64 instantiation is bit-identical to the proven R3 kernel.
// ---------------------------------------------------------------------------
template <int BN, bool BIAS, bool GELU, bool RESID>
__global__ void __launch_bounds__(256, 2) mma_gemm(
    const float* __restrict__ A,
    const __nv_bfloat16* __restrict__ Bh_g,
    const __nv_bfloat16* __restrict__ Bl_g,
    const float* __restrict__ bias,
    float* __restrict__ C,
    int rows, int K, int ncols)
{
    constexpr int BM = 128, BK = 32, LD = 40;
    constexpr int JN = BN / 16;   // 8-col groups per warp (8 or 4)
    constexpr int NP = BN / 32;   // 16-row B ldsm pairs (4 or 2)
    __shared__ __nv_bfloat16 sAh[BM * LD];
    __shared__ __nv_bfloat16 sAl[BM * LD];
    __shared__ __nv_bfloat16 sBh[BN * LD];
    __shared__ __nv_bfloat16 sBl[BN * LD];

    int tid = threadIdx.x;
    int lane = tid & 31;
    int wid = tid >> 5;
    int wm = wid & 3;          // m offset wm*32
    int wn = wid >> 2;         // n offset wn*(BN/2)
    int r0 = blockIdx.y * BM;
    int c0 = blockIdx.x * BN;

    float acc[2][JN][4];
#pragma unroll
    for (int i = 0; i < 2; i++)
#pragma unroll
        for (int j = 0; j < JN; j++)
#pragma unroll
            for (int k = 0; k < 4; k++) acc[i][j][k] = 0.f;

    uint32_t aH = smem_u32(sAh), aL = smem_u32(sAl);
    uint32_t bH = smem_u32(sBh), bL = smem_u32(sBl);

    int a_r = lane & 15;
    int a_c = (lane >> 4) * 8;
    int b_n = ((lane >> 4) * 8) + (lane & 7);
    int b_k = ((lane >> 3) & 1) * 8;

    int nkc = K / BK;
    for (int kc = 0; kc < nkc; kc++) {
        int k0 = kc * BK;
        // --- stage A [128 x 32] fp32 -> bf16 hi/lo ---
        {
            int c4 = tid & 7;
            int rr = tid >> 3;
#pragma unroll
            for (int q = 0; q < 4; q++) {
                int row = rr + q * 32;
                int gr = r0 + row;
                float4 a = make_float4(0.f, 0.f, 0.f, 0.f);
                if (gr < rows)
                    a = *reinterpret_cast<const float4*>(A + (size_t)gr * K + k0 + c4 * 4);
                __nv_bfloat16 h0, h1, h2, h3, l0, l1, l2, l3;
                split_bf16(a.x, h0, l0);
                split_bf16(a.y, h1, l1);
                split_bf16(a.z, h2, l2);
                split_bf16(a.w, h3, l3);
                uint2 uh = make_uint2(
                    ((uint32_t)__bfloat16_as_ushort(h1) << 16) | __bfloat16_as_ushort(h0),
                    ((uint32_t)__bfloat16_as_ushort(h3) << 16) | __bfloat16_as_ushort(h2));
                uint2 ul = make_uint2(
                    ((uint32_t)__bfloat16_as_ushort(l1) << 16) | __bfloat16_as_ushort(l0),
                    ((uint32_t)__bfloat16_as_ushort(l3) << 16) | __bfloat16_as_ushort(l2));
                *reinterpret_cast<uint2*>(sAh + row * LD + c4 * 4) = uh;
                *reinterpret_cast<uint2*>(sAl + row * LD + c4 * 4) = ul;
            }
        }
        // --- stage B [BN x 32] bf16 hi/lo (copy) ---
#pragma unroll
        for (int q = 0; q < BN / 64; q++) {
            int ch = tid + q * 256;
            int rowb = ch >> 2;
            int c8 = ch & 3;
            size_t g = (size_t)(c0 + rowb) * K + k0 + c8 * 8;
            *reinterpret_cast<uint4*>(sBh + rowb * LD + c8 * 8) =
                *reinterpret_cast<const uint4*>(Bh_g + g);
            *reinterpret_cast<uint4*>(sBl + rowb * LD + c8 * 8) =
                *reinterpret_cast<const uint4*>(Bl_g + g);
        }
        __syncthreads();

#pragma unroll
        for (int kk = 0; kk < 2; kk++) {
            uint32_t ah[2][4], al[2][4], bh[NP][4], bl[NP][4];
#pragma unroll
            for (int im = 0; im < 2; im++) {
                uint32_t off = (uint32_t)(((wm * 32 + im * 16 + a_r) * LD + kk * 16 + a_c) * 2);
                ldsm4(ah[im][0], ah[im][1], ah[im][2], ah[im][3], aH + off);
                ldsm4(al[im][0], al[im][1], al[im][2], al[im][3], aL + off);
            }
#pragma unroll
            for (int jp = 0; jp < NP; jp++) {
                uint32_t off = (uint32_t)(((wn * (BN / 2) + jp * 16 + b_n) * LD + kk * 16 + b_k) * 2);
                ldsm4(bh[jp][0], bh[jp][1], bh[jp][2], bh[jp][3], bH + off);
                ldsm4(bl[jp][0], bl[jp][1], bl[jp][2], bl[jp][3], bL + off);
            }
#pragma unroll
            for (int im = 0; im < 2; im++)
#pragma unroll
                for (int jn = 0; jn < JN; jn++) {
                    const uint32_t* pbh = &bh[jn >> 1][(jn & 1) * 2];
                    const uint32_t* pbl = &bl[jn >> 1][(jn & 1) * 2];
                    mma_bf16(acc[im][jn], ah[im], pbh);
                    mma_bf16(acc[im][jn], ah[im], pbl);
                    mma_bf16(acc[im][jn], al[im], pbh);
                }
        }
        __syncthreads();
    }

    // --- epilogue ---
#pragma unroll
    for (int im = 0; im < 2; im++) {
        int rowa = r0 + wm * 32 + im * 16 + (lane >> 2);
        int rowb2 = rowa + 8;
#pragma unroll
        for (int jn = 0; jn < JN; jn++) {
            int col = c0 + wn * (BN / 2) + jn * 8 + (lane & 3) * 2;
            float2 bv = make_float2(0.f, 0.f);
            if (BIAS) bv = *reinterpret_cast<const float2*>(bias + col);
#pragma unroll
            for (int h = 0; h < 2; h++) {
                int row = h ? rowb2 : rowa;
                if (row >= rows) continue;
                float vx = acc[im][jn][h * 2 + 0];
                float vy = acc[im][jn][h * 2 + 1];
                if (BIAS) { vx += bv.x; vy += bv.y; }
                if (GELU) { vx = gelu_f(vx); vy = gelu_f(vy); }
                float* p = C + (size_t)row * ncols + col;
                if (RESID) {
                    float2 old = *reinterpret_cast<const float2*>(p);
                    vx += old.x; vy += old.y;
                }
                *reinterpret_cast<float2*>(p) = make_float2(vx, vy);
            }
        }
    }
}

// ---------------------------------------------------------------------------
// Embedding init
// ---------------------------------------------------------------------------
__global__ void embed_kernel(const int* __restrict__ z,
                             const float* __restrict__ table,
                             const float* __restrict__ W,
                             const float* __restrict__ b,
                             float* __restrict__ x, int N) {
    int n = blockIdx.x;
    if (n >= N) return;
    int d = threadIdx.x;
    int t = z[n];
    float acc = b[d];
#pragma unroll
    for (int h = 0; h < 5; h++) acc += table[t * 5 + h] * W[h * 256 + d];
    x[(size_t)n * 256 + d] = acc;
}

// ---------------------------------------------------------------------------
// Bessel RBF with polynomial envelope (p=5): sincos + Chebyshev recurrence
// ---------------------------------------------------------------------------
__global__ void rbf_kernel(const int* __restrict__ ei,
                           const float* __restrict__ pos,
                           const float* __restrict__ freqs,
                           int E) {
    int e = blockIdx.x * blockDim.x + threadIdx.x;
    if (e >= E) return;
    int i = ei[e];
    int j = ei[E + e];
    float dx = pos[i * 3 + 0] - pos[j * 3 + 0];
    float dy = pos[i * 3 + 1] - pos[j * 3 + 1];
    float dz = pos[i * 3 + 2] - pos[j * 3 + 2];
    float dist = sqrtf(dx * dx + dy * dy + dz * dz + 1e-12f);
    float x = dist * 0.2f;
    float x2 = x * x;
    float x4 = x2 * x2;
    float env = 1.0f / x + (-21.0f) * x4 + 35.0f * x4 * x + (-15.0f) * x4 * x2;

    float f = freqs[0] * x;          // pi * x
    float s1, c1;
    sincosf(f, &s1, &c1);
    float twoc = 2.0f * c1;
    float sprev = 0.f, scur = s1;
    float* out = g_rbf + (size_t)e * 12;
#pragma unroll
    for (int r = 0; r < 12; r++) {
        out[r] = env * scur;
        float snext = twoc * scur - sprev;
        sprev = scur;
        scur = snext;
    }
}

// ---------------------------------------------------------------------------
// Edge messages + scatter: 16 threads/edge, vector red.global.add.v4.f32
// ---------------------------------------------------------------------------
__global__ void edge_msg_kernel(const int* __restrict__ ei,
                                const float* __restrict__ Wrbf,  // [12,64]
                                int E) {
    __shared__ float sW[12 * 64];
    for (int t = threadIdx.x; t < 12 * 64; t += blockDim.x) sW[t] = Wrbf[t];
    __syncthreads();

    int gt = blockIdx.x * blockDim.x + threadIdx.x;
    int e = gt >> 4;
    if (e >= E) return;
    int sub = gt & 15;
    int m0 = sub * 4;

    int i = ei[e];
    int j = ei[E + e];

    float gx = 0.f, gy = 0.f, gz = 0.f, gw = 0.f;
#pragma unroll
    for (int r = 0; r < 12; r++) {
        float rv = __ldg(&g_rbf[(size_t)e * 12 + r]);
        const float* w = &sW[r * 64 + m0];
        gx = fmaf(rv, w[0], gx);
        gy = fmaf(rv, w[1], gy);
        gz = fmaf(rv, w[2], gz);
        gw = fmaf(rv, w[3], gw);
    }
    const float4 vj = *reinterpret_cast<const float4*>(g_v + (size_t)j * 64 + m0);
    float vx = vj.x * gx, vy = vj.y * gy, vz = vj.z * gz, vw = vj.w * gw;
    float* dst = g_agg + (size_t)i * 64 + m0;
    asm volatile("red.global.add.v4.f32 [%0], {%1, %2, %3, %4};"
                 :: "l"(dst), "f"(vx), "f"(vy), "f"(vz), "f"(vw) : "memory");
}

// ---------------------------------------------------------------------------
// Launcher
// ---------------------------------------------------------------------------
extern "C" void kernel_launch(void* const* d_in, const int* in_sizes, int n_in,
                              void* d_out, int out_size) {
    const int* z = (const int*)d_in[0];
    const float* pos = (const float*)d_in[1];
    const int* ei = (const int*)d_in[4];
    const float* emb_table = (const float*)d_in[5];
    const float* emb_W = (const float*)d_in[6];
    const float* emb_b = (const float*)d_in[7];
    const float* freqs = (const float*)d_in[8];
    const float* fc0_W = (const float*)d_in[9];
    const float* fc0_b = (const float*)d_in[10];
    const float* conv_Wv = (const float*)d_in[11];
    const float* conv_Wrbf = (const float*)d_in[12];
    const float* conv_Wout = (const float*)d_in[13];
    const float* fc_W = (const float*)d_in[14];
    const float* fc_b = (const float*)d_in[15];

    int N = in_sizes[1] / 3;   // 50000
    int E = in_sizes[4] / 2;   // 800000

    float* x = (float*)d_out;

    float *tmp, *vbuf, *agg;
    __nv_bfloat16 *wh, *wl;
    cudaGetSymbolAddress((void**)&tmp, g_tmp);
    cudaGetSymbolAddress((void**)&vbuf, g_v);
    cudaGetSymbolAddress((void**)&agg, g_agg);
    cudaGetSymbolAddress((void**)&wh, g_wh);
    cudaGetSymbolAddress((void**)&wl, g_wl);

    dim3 gridD(2, (N + 127) / 128);   // ncols=256, BN=128
    dim3 gridM(1, (N + 127) / 128);   // ncols=64,  BN=64

    // 1. init embedding (launch #1, no dependency on conv_w)
    embed_kernel<<<N, 256>>>(z, emb_table, emb_W, emb_b, x, N);

    // 2. weight conversion (launches #2-#5)
    {
        int T = 2 * 65536;
        conv_w_kernel<<<(T + 255) / 256, 256>>>(fc0_W, wh, wl, 256, 256, T);
        T = 8 * 65536;
        conv_w_kernel<<<(T + 255) / 256, 256>>>(fc_W, wh + 2 * 65536, wl + 2 * 65536, 256, 256, T);
        T = 4 * 16384;
        conv_w_kernel<<<(T + 255) / 256, 256>>>(conv_Wv, wh + 655360, wl + 655360, 256, 64, T);
        conv_w_kernel<<<(T + 255) / 256, 256>>>(conv_Wout, wh + 655360 + 65536,
                                                wl + 655360 + 65536, 64, 256, T);
    }

    // 3. init FC block (launch #6 = big GEMM -> ncu captures this)
    mma_gemm<128, true, true, false><<<gridD, 256>>>(x, wh, wl, fc0_b, tmp, N, 256, 256);
    mma_gemm<128, true, true, false><<<gridD, 256>>>(tmp, wh + 65536, wl + 65536,
                                                     fc0_b + 256, x, N, 256, 256);

    // 4. radial basis
    rbf_kernel<<<(E + 255) / 256, 256>>>(ei, pos, freqs, E);

    // 5. interaction blocks
    for (int n = 0; n < 4; n++) {
        cudaMemsetAsync(agg, 0, (size_t)N * 64 * sizeof(float));

        // v = x @ Wv[n]
        mma_gemm<64, false, false, false><<<gridM, 256>>>(
            x, wh + 655360 + n * 16384, wl + 655360 + n * 16384, nullptr,
            vbuf, N, 256, 64);

        // gated messages + vector-red scatter
        edge_msg_kernel<<<(E * 16 + 255) / 256, 256>>>(
            ei, conv_Wrbf + (size_t)n * 12 * 64, E);

        // x = x + agg @ Wout[n]
        mma_gemm<128, false, false, true><<<gridD, 256>>>(
            agg, wh + 655360 + 65536 + n * 16384, wl + 655360 + 65536 + n * 16384,
            nullptr, x, N, 64, 256);

        // FC block
        const __nv_bfloat16* W0h = wh + (size_t)(2 + 2 * n) * 65536;
        const __nv_bfloat16* W0l = wl + (size_t)(2 + 2 * n) * 65536;
        const __nv_bfloat16* W1h = wh + (size_t)(3 + 2 * n) * 65536;
        const __nv_bfloat16* W1l = wl + (size_t)(3 + 2 * n) * 65536;
        const float* b0 = fc_b + (size_t)n * 2 * 256;
        const float* b1 = b0 + 256;
        mma_gemm<128, true, true, false><<<gridD, 256>>>(x, W0h, W0l, b0, tmp, N, 256, 256);
        mma_gemm<128, true, true, true><<<gridD, 256>>>(tmp, W1h, W1l, b1, x, N, 256, 256);
    }
}

// round 11
// speedup vs baseline: 1.1813x; 1.0714x over previous
#include <cuda_runtime.h>
#include <cuda_bf16.h>
#include <math.h>
#include <stdint.h>

#define NN 50000
#define EE 800000

// ---------------- scratch (no cudaMalloc allowed) ----------------
__device__ __align__(16) float g_tmp[NN * 256];
__device__ __align__(16) float g_v[NN * 64];
__device__ __align__(16) float g_agg[NN * 64];
__device__ __align__(16) float g_rbf[EE * 12];
// bf16 hi/lo transposed weights: 10x[256x256] + 8x[64x256 / 256x64]
__device__ __align__(16) __nv_bfloat16 g_wh[10 * 65536 + 8 * 16384];
__device__ __align__(16) __nv_bfloat16 g_wl[10 * 65536 + 8 * 16384];

__device__ __forceinline__ uint32_t smem_u32(const void* p) {
    uint32_t a;
    asm("{ .reg .u64 t; cvta.to.shared.u64 t, %1; cvt.u32.u64 %0, t; }" : "=r"(a) : "l"(p));
    return a;
}

__device__ __forceinline__ void ldsm4(uint32_t& r0, uint32_t& r1, uint32_t& r2,
                                      uint32_t& r3, uint32_t addr) {
    asm volatile("ldmatrix.sync.aligned.m8n8.x4.shared.b16 {%0,%1,%2,%3}, [%4];"
                 : "=r"(r0), "=r"(r1), "=r"(r2), "=r"(r3) : "r"(addr));
}

__device__ __forceinline__ void mma_bf16(float* c, const uint32_t* a, const uint32_t* b) {
    asm volatile(
        "mma.sync.aligned.m16n8k16.row.col.f32.bf16.bf16.f32 "
        "{%0,%1,%2,%3}, {%4,%5,%6,%7}, {%8,%9}, {%0,%1,%2,%3};"
        : "+f"(c[0]), "+f"(c[1]), "+f"(c[2]), "+f"(c[3])
        : "r"(a[0]), "r"(a[1]), "r"(a[2]), "r"(a[3]), "r"(b[0]), "r"(b[1]));
}

__device__ __forceinline__ float gelu_f(float x) {
    float x3 = x * x * x;
    float t = tanhf(0.7978845608028654f * (x + 0.044715f * x3));
    return 0.5f * x * (1.0f + t);
}

__device__ __forceinline__ void split_bf16(float v, __nv_bfloat16& h, __nv_bfloat16& l) {
    h = __float2bfloat16(v);
    l = __float2bfloat16(v - __bfloat162float(h));
}

// ---------------------------------------------------------------------------
// Weight convert: W [nm][K x N] fp32 -> out [nm][N x K] bf16 hi/lo (transposed)
// ---------------------------------------------------------------------------
__global__ void conv_w_kernel(const float* __restrict__ W,
                              __nv_bfloat16* __restrict__ oh,
                              __nv_bfloat16* __restrict__ ol,
                              int K, int Ncols, int total) {
    int idx = blockIdx.x * blockDim.x + threadIdx.x;
    if (idx >= total) return;
    int kn = K * Ncols;
    int m = idx / kn;
    int r = idx - m * kn;
    int n = r / K;
    int k = r - n * K;
    float w = W[(size_t)m * kn + (size_t)k * Ncols + n];
    split_bf16(w, oh[idx], ol[idx]);
}

// ---------------------------------------------------------------------------
// HMMA GEMM (R3-proven): CTA tile 128x64, BK=32, 256 threads, 8 warps.
// 3-product split: Ah*Bh + Ah*Bl + Al*Bh, fp32 accumulate.
// ---------------------------------------------------------------------------
template <bool BIAS, bool GELU, bool RESID>
__global__ void __launch_bounds__(256) mma_gemm(
    const float* __restrict__ A,
    const __nv_bfloat16* __restrict__ Bh_g,
    const __nv_bfloat16* __restrict__ Bl_g,
    const float* __restrict__ bias,
    float* __restrict__ C,
    int rows, int K, int ncols)
{
    constexpr int BM = 128, BN = 64, BK = 32, LD = 40;
    __shared__ __nv_bfloat16 sAh[BM * LD];
    __shared__ __nv_bfloat16 sAl[BM * LD];
    __shared__ __nv_bfloat16 sBh[BN * LD];
    __shared__ __nv_bfloat16 sBl[BN * LD];

    int tid = threadIdx.x;
    int lane = tid & 31;
    int wid = tid >> 5;
    int wm = wid & 3;
    int wn = wid >> 2;
    int r0 = blockIdx.y * BM;
    int c0 = blockIdx.x * BN;

    float acc[2][4][4];
#pragma unroll
    for (int i = 0; i < 2; i++)
#pragma unroll
        for (int j = 0; j < 4; j++)
#pragma unroll
            for (int k = 0; k < 4; k++) acc[i][j][k] = 0.f;

    uint32_t aH = smem_u32(sAh), aL = smem_u32(sAl);
    uint32_t bH = smem_u32(sBh), bL = smem_u32(sBl);

    int a_r = lane & 15;
    int a_c = (lane >> 4) * 8;
    int b_n = ((lane >> 4) * 8) + (lane & 7);
    int b_k = ((lane >> 3) & 1) * 8;

    int nkc = K / BK;
    for (int kc = 0; kc < nkc; kc++) {
        int k0 = kc * BK;
        {
            int c4 = tid & 7;
            int rr = tid >> 3;
#pragma unroll
            for (int q = 0; q < 4; q++) {
                int row = rr + q * 32;
                int gr = r0 + row;
                float4 a = make_float4(0.f, 0.f, 0.f, 0.f);
                if (gr < rows)
                    a = *reinterpret_cast<const float4*>(A + (size_t)gr * K + k0 + c4 * 4);
                __nv_bfloat16 h0, h1, h2, h3, l0, l1, l2, l3;
                split_bf16(a.x, h0, l0);
                split_bf16(a.y, h1, l1);
                split_bf16(a.z, h2, l2);
                split_bf16(a.w, h3, l3);
                uint2 uh = make_uint2(
                    ((uint32_t)__bfloat16_as_ushort(h1) << 16) | __bfloat16_as_ushort(h0),
                    ((uint32_t)__bfloat16_as_ushort(h3) << 16) | __bfloat16_as_ushort(h2));
                uint2 ul = make_uint2(
                    ((uint32_t)__bfloat16_as_ushort(l1) << 16) | __bfloat16_as_ushort(l0),
                    ((uint32_t)__bfloat16_as_ushort(l3) << 16) | __bfloat16_as_ushort(l2));
                *reinterpret_cast<uint2*>(sAh + row * LD + c4 * 4) = uh;
                *reinterpret_cast<uint2*>(sAl + row * LD + c4 * 4) = ul;
            }
        }
        {
            int rowb = tid >> 2;
            int c8 = tid & 3;
            size_t g = (size_t)(c0 + rowb) * K + k0 + c8 * 8;
            *reinterpret_cast<uint4*>(sBh + rowb * LD + c8 * 8) =
                *reinterpret_cast<const uint4*>(Bh_g + g);
            *reinterpret_cast<uint4*>(sBl + rowb * LD + c8 * 8) =
                *reinterpret_cast<const uint4*>(Bl_g + g);
        }
        __syncthreads();

#pragma unroll
        for (int kk = 0; kk < 2; kk++) {
            uint32_t ah[2][4], al[2][4], bh[2][4], bl[2][4];
#pragma unroll
            for (int im = 0; im < 2; im++) {
                uint32_t off = (uint32_t)(((wm * 32 + im * 16 + a_r) * LD + kk * 16 + a_c) * 2);
                ldsm4(ah[im][0], ah[im][1], ah[im][2], ah[im][3], aH + off);
                ldsm4(al[im][0], al[im][1], al[im][2], al[im][3], aL + off);
            }
#pragma unroll
            for (int jp = 0; jp < 2; jp++) {
                uint32_t off = (uint32_t)(((wn * 32 + jp * 16 + b_n) * LD + kk * 16 + b_k) * 2);
                ldsm4(bh[jp][0], bh[jp][1], bh[jp][2], bh[jp][3], bH + off);
                ldsm4(bl[jp][0], bl[jp][1], bl[jp][2], bl[jp][3], bL + off);
            }
#pragma unroll
            for (int im = 0; im < 2; im++)
#pragma unroll
                for (int jn = 0; jn < 4; jn++) {
                    const uint32_t* pbh = &bh[jn >> 1][(jn & 1) * 2];
                    const uint32_t* pbl = &bl[jn >> 1][(jn & 1) * 2];
                    mma_bf16(acc[im][jn], ah[im], pbh);
                    mma_bf16(acc[im][jn], ah[im], pbl);
                    mma_bf16(acc[im][jn], al[im], pbh);
                }
        }
        __syncthreads();
    }

#pragma unroll
    for (int im = 0; im < 2; im++) {
        int rowa = r0 + wm * 32 + im * 16 + (lane >> 2);
        int rowb2 = rowa + 8;
#pragma unroll
        for (int jn = 0; jn < 4; jn++) {
            int col = c0 + wn * 32 + jn * 8 + (lane & 3) * 2;
            float2 bv = make_float2(0.f, 0.f);
            if (BIAS) bv = *reinterpret_cast<const float2*>(bias + col);
#pragma unroll
            for (int h = 0; h < 2; h++) {
                int row = h ? rowb2 : rowa;
                if (row >= rows) continue;
                float vx = acc[im][jn][h * 2 + 0];
                float vy = acc[im][jn][h * 2 + 1];
                if (BIAS) { vx += bv.x; vy += bv.y; }
                if (GELU) { vx = gelu_f(vx); vy = gelu_f(vy); }
                float* p = C + (size_t)row * ncols + col;
                if (RESID) {
                    float2 old = *reinterpret_cast<const float2*>(p);
                    vx += old.x; vy += old.y;
                }
                *reinterpret_cast<float2*>(p) = make_float2(vx, vy);
            }
        }
    }
}

// ---------------------------------------------------------------------------
// Embedding init
// ---------------------------------------------------------------------------
__global__ void embed_kernel(const int* __restrict__ z,
                             const float* __restrict__ table,
                             const float* __restrict__ W,
                             const float* __restrict__ b,
                             float* __restrict__ x, int N) {
    int n = blockIdx.x;
    if (n >= N) return;
    int d = threadIdx.x;
    int t = z[n];
    float acc = b[d];
#pragma unroll
    for (int h = 0; h < 5; h++) acc += table[t * 5 + h] * W[h * 256 + d];
    x[(size_t)n * 256 + d] = acc;
}

// ---------------------------------------------------------------------------
// Bessel RBF with polynomial envelope (p=5): sincos + Chebyshev recurrence
// (numerics validated in R9/R10 passing runs)
// ---------------------------------------------------------------------------
__global__ void rbf_kernel(const int* __restrict__ ei,
                           const float* __restrict__ pos,
                           const float* __restrict__ freqs,
                           int E) {
    int e = blockIdx.x * blockDim.x + threadIdx.x;
    if (e >= E) return;
    int i = ei[e];
    int j = ei[E + e];
    float dx = pos[i * 3 + 0] - pos[j * 3 + 0];
    float dy = pos[i * 3 + 1] - pos[j * 3 + 1];
    float dz = pos[i * 3 + 2] - pos[j * 3 + 2];
    float dist = sqrtf(dx * dx + dy * dy + dz * dz + 1e-12f);
    float x = dist * 0.2f;
    float x2 = x * x;
    float x4 = x2 * x2;
    float env = 1.0f / x + (-21.0f) * x4 + 35.0f * x4 * x + (-15.0f) * x4 * x2;

    float f = freqs[0] * x;          // pi * x
    float s1, c1;
    sincosf(f, &s1, &c1);
    float twoc = 2.0f * c1;
    float sprev = 0.f, scur = s1;
    float* out = g_rbf + (size_t)e * 12;
#pragma unroll
    for (int r = 0; r < 12; r++) {
        out[r] = env * scur;
        float snext = twoc * scur - sprev;
        sprev = scur;
        scur = snext;
    }
}

// ---------------------------------------------------------------------------
// Edge messages + scatter: 16 threads/edge, rbf via 3x LDG.128,
// vector red.global.add.v4.f32
// ---------------------------------------------------------------------------
__global__ void edge_msg_kernel(const int* __restrict__ ei,
                                const float* __restrict__ Wrbf,  // [12,64]
                                int E) {
    __shared__ float sW[12 * 64];
    for (int t = threadIdx.x; t < 12 * 64; t += blockDim.x) sW[t] = Wrbf[t];
    __syncthreads();

    int gt = blockIdx.x * blockDim.x + threadIdx.x;
    int e = gt >> 4;
    if (e >= E) return;
    int sub = gt & 15;
    int m0 = sub * 4;

    int i = ei[e];
    int j = ei[E + e];

    const float4* rp = reinterpret_cast<const float4*>(g_rbf + (size_t)e * 12);
    float4 f0 = __ldg(rp);
    float4 f1 = __ldg(rp + 1);
    float4 f2 = __ldg(rp + 2);
    float r[12] = {f0.x, f0.y, f0.z, f0.w, f1.x, f1.y, f1.z, f1.w,
                   f2.x, f2.y, f2.z, f2.w};

    float gx = 0.f, gy = 0.f, gz = 0.f, gw = 0.f;
#pragma unroll
    for (int rr = 0; rr < 12; rr++) {
        const float* w = &sW[rr * 64 + m0];
        gx = fmaf(r[rr], w[0], gx);
        gy = fmaf(r[rr], w[1], gy);
        gz = fmaf(r[rr], w[2], gz);
        gw = fmaf(r[rr], w[3], gw);
    }
    const float4 vj = *reinterpret_cast<const float4*>(g_v + (size_t)j * 64 + m0);
    float vx = vj.x * gx, vy = vj.y * gy, vz = vj.z * gz, vw = vj.w * gw;
    float* dst = g_agg + (size_t)i * 64 + m0;
    asm volatile("red.global.add.v4.f32 [%0], {%1, %2, %3, %4};"
                 :: "l"(dst), "f"(vx), "f"(vy), "f"(vz), "f"(vw) : "memory");
}

// ---------------------------------------------------------------------------
// Launcher
// ---------------------------------------------------------------------------
extern "C" void kernel_launch(void* const* d_in, const int* in_sizes, int n_in,
                              void* d_out, int out_size) {
    const int* z = (const int*)d_in[0];
    const float* pos = (const float*)d_in[1];
    const int* ei = (const int*)d_in[4];
    const float* emb_table = (const float*)d_in[5];
    const float* emb_W = (const float*)d_in[6];
    const float* emb_b = (const float*)d_in[7];
    const float* freqs = (const float*)d_in[8];
    const float* fc0_W = (const float*)d_in[9];
    const float* fc0_b = (const float*)d_in[10];
    const float* conv_Wv = (const float*)d_in[11];
    const float* conv_Wrbf = (const float*)d_in[12];
    const float* conv_Wout = (const float*)d_in[13];
    const float* fc_W = (const float*)d_in[14];
    const float* fc_b = (const float*)d_in[15];

    int N = in_sizes[1] / 3;   // 50000
    int E = in_sizes[4] / 2;   // 800000

    float* x = (float*)d_out;

    float *tmp, *vbuf, *agg;
    __nv_bfloat16 *wh, *wl;
    cudaGetSymbolAddress((void**)&tmp, g_tmp);
    cudaGetSymbolAddress((void**)&vbuf, g_v);
    cudaGetSymbolAddress((void**)&agg, g_agg);
    cudaGetSymbolAddress((void**)&wh, g_wh);
    cudaGetSymbolAddress((void**)&wl, g_wl);

    // ---- weight conversion (hi/lo bf16, transposed) ----
    {
        int T = 2 * 65536;
        conv_w_kernel<<<(T + 255) / 256, 256>>>(fc0_W, wh, wl, 256, 256, T);
        T = 8 * 65536;
        conv_w_kernel<<<(T + 255) / 256, 256>>>(fc_W, wh + 2 * 65536, wl + 2 * 65536, 256, 256, T);
        T = 4 * 16384;
        conv_w_kernel<<<(T + 255) / 256, 256>>>(conv_Wv, wh + 655360, wl + 655360, 256, 64, T);
        conv_w_kernel<<<(T + 255) / 256, 256>>>(conv_Wout, wh + 655360 + 65536,
                                                wl + 655360 + 65536, 64, 256, T);
    }

    dim3 gridD(4, (N + 127) / 128);   // ncols=256
    dim3 gridM(1, (N + 127) / 128);   // ncols=64

    // 1. init embedding
    embed_kernel<<<N, 256>>>(z, emb_table, emb_W, emb_b, x, N);

    // 2. init FC block
    mma_gemm<true, true, false><<<gridD, 256>>>(x, wh, wl, fc0_b, tmp, N, 256, 256);
    mma_gemm<true, true, false><<<gridD, 256>>>(tmp, wh + 65536, wl + 65536,
                                                fc0_b + 256, x, N, 256, 256);

    // 3. radial basis
    rbf_kernel<<<(E + 255) / 256, 256>>>(ei, pos, freqs, E);

    // 4. interaction blocks
    for (int n = 0; n < 4; n++) {
        cudaMemsetAsync(agg, 0, (size_t)N * 64 * sizeof(float));

        // v = x @ Wv[n]
        mma_gemm<false, false, false><<<gridM, 256>>>(
            x, wh + 655360 + n * 16384, wl + 655360 + n * 16384, nullptr,
            vbuf, N, 256, 64);

        // gated messages + vector-red scatter
        edge_msg_kernel<<<(E * 16 + 255) / 256, 256>>>(
            ei, conv_Wrbf + (size_t)n * 12 * 64, E);

        // x = x + agg @ Wout[n]
        mma_gemm<false, false, true><<<gridD, 256>>>(
            agg, wh + 655360 + 65536 + n * 16384, wl + 655360 + 65536 + n * 16384,
            nullptr, x, N, 64, 256);

        // FC block
        const __nv_bfloat16* W0h = wh + (size_t)(2 + 2 * n) * 65536;
        const __nv_bfloat16* W0l = wl + (size_t)(2 + 2 * n) * 65536;
        const __nv_bfloat16* W1h = wh + (size_t)(3 + 2 * n) * 65536;
        const __nv_bfloat16* W1l = wl + (size_t)(3 + 2 * n) * 65536;
        const float* b0 = fc_b + (size_t)n * 2 * 256;
        const float* b1 = b0 + 256;
        mma_gemm<true, true, false><<<gridD, 256>>>(x, W0h, W0l, b0, tmp, N, 256, 256);
        mma_gemm<true, true, true><<<gridD, 256>>>(tmp, W1h, W1l, b1, x, N, 256, 256);
    }
}